// round 15
// baseline (speedup 1.0000x reference)
#include <cuda_runtime.h>
#include <cuda_fp16.h>
#include <cstdint>
#include <cstddef>

// MultiAgentSEPSNetwork: 8 agents x (4096,256)->1024->1024->512 MLP,
// per-agent net via seps_idx (int32 &3).
//
// Round 15: R14 GEMM mainloop untouched (CTA 128x128, 4 warps 64x64, KT=64,
// 2-stage, 2 CTAs/SM; single-term fp16, rel_err 5.1e-4). Epilogue now stages
// results in the free pipeline smem (conflict-free stride-68 layout) and
// stores with fully-coalesced 128-bit STG (was 64 scattered STG.64/thread).

namespace seps {

constexpr int NA = 8;
constexpr int NE = 4096;

// ---- persistent device scratch ----
__device__ uint32_t g_xh [(size_t)NA * NE * 128];    // x fp16 [M][K2] words
__device__ uint32_t g_w1h[(size_t)4 * 1024 * 128];   // W^T fp16 [S][N][K2]
__device__ uint32_t g_w2h[(size_t)4 * 1024 * 512];
__device__ uint32_t g_w3h[(size_t)4 * 512 * 512];
__device__ uint32_t g_h1h[(size_t)NA * NE * 512];    // h fp16 [M][K2]
__device__ uint32_t g_h2h[(size_t)NA * NE * 512];

__device__ __forceinline__ uint32_t smem_u32(const void* p) {
    uint32_t a;
    asm("{ .reg .u64 t; cvta.to.shared.u64 t, %1; cvt.u32.u64 %0, t; }" : "=r"(a) : "l"(p));
    return a;
}
__device__ __forceinline__ uint32_t pack2h(float v0, float v1) {
    __half h0 = __float2half_rn(v0), h1 = __float2half_rn(v1);
    return (uint32_t)__half_as_ushort(h0) | ((uint32_t)__half_as_ushort(h1) << 16);
}
__device__ __forceinline__ void cp_async16(uint32_t dst, const void* src) {
    asm volatile("cp.async.cg.shared.global [%0], [%1], 16;" :: "r"(dst), "l"(src));
}
__device__ __forceinline__ void cp_commit() { asm volatile("cp.async.commit_group;"); }
template<int N> __device__ __forceinline__ void cp_wait() {
    asm volatile("cp.async.wait_group %0;" :: "n"(N));
}
__device__ __forceinline__ void mma_f16(float* c, const uint32_t* a, const uint32_t* b) {
    asm volatile(
        "mma.sync.aligned.m16n8k16.row.col.f32.f16.f16.f32 "
        "{%0,%1,%2,%3}, {%4,%5,%6,%7}, {%8,%9}, {%0,%1,%2,%3};"
        : "+f"(c[0]), "+f"(c[1]), "+f"(c[2]), "+f"(c[3])
        : "r"(a[0]), "r"(a[1]), "r"(a[2]), "r"(a[3]),
          "r"(b[0]), "r"(b[1]));
}
__device__ __forceinline__ void ldsm_x4(uint32_t& r0, uint32_t& r1, uint32_t& r2,
                                        uint32_t& r3, uint32_t addr) {
    asm volatile("ldmatrix.sync.aligned.m8n8.x4.shared.b16 {%0,%1,%2,%3}, [%4];"
                 : "=r"(r0), "=r"(r1), "=r"(r2), "=r"(r3) : "r"(addr));
}

// ---- prepass ----
__global__ void pack_act4(const float4* __restrict__ in, uint2* __restrict__ hi, int n4) {
    int i = blockIdx.x * blockDim.x + threadIdx.x;
    if (i < n4) {
        float4 v = in[i];
        hi[i] = make_uint2(pack2h(v.x, v.y), pack2h(v.z, v.w));
    }
}

// Fused tiled transpose+pack for all three weight tensors.
__global__ __launch_bounds__(256)
void pack_wgt_fused(const float* __restrict__ W1, uint32_t* __restrict__ o1,
                    const float* __restrict__ W2, uint32_t* __restrict__ o2,
                    const float* __restrict__ W3, uint32_t* __restrict__ o3) {
    __shared__ uint32_t tile[32][33];
    const int layer = blockIdx.z >> 2;
    const int s     = blockIdx.z & 3;
    int K2, N;
    const float* src;
    uint32_t* dst;
    if (layer == 0)      { K2 = 128; N = 1024; src = W1; dst = o1; }
    else if (layer == 1) { K2 = 512; N = 1024; src = W2; dst = o2; }
    else                 { K2 = 512; N =  512; src = W3; dst = o3; }

    const int kw0 = blockIdx.x * 32;
    const int n0  = blockIdx.y * 32;
    if (kw0 >= K2 || n0 >= N) return;

    const int tx = threadIdx.x & 31;
    const int ty = threadIdx.x >> 5;
    const float* ws = src + (size_t)s * (2 * K2) * N;
    #pragma unroll
    for (int r = 0; r < 32; r += 8) {
        const int kw = kw0 + r + ty;
        const float v0 = ws[(size_t)(2 * kw    ) * N + n0 + tx];
        const float v1 = ws[(size_t)(2 * kw + 1) * N + n0 + tx];
        tile[tx][r + ty] = pack2h(v0, v1);
    }
    __syncthreads();
    uint32_t* wd = dst + (size_t)s * N * K2;
    #pragma unroll
    for (int r = 0; r < 32; r += 8) {
        const int n = n0 + r + ty;
        wd[(size_t)n * K2 + kw0 + tx] = tile[r + ty][tx];
    }
}

// ---- GEMM: CTA 128x128, 4 warps (2Mx2N, 64x64 each), KT=64, 2-stage ----
template<int K, int NOUT, bool RELU, bool PACK_OUT>
__global__ __launch_bounds__(128, 2)
void gemm_f16(const uint32_t* __restrict__ Ah, const uint32_t* __restrict__ Bh,
              const float* __restrict__ bias, const int* __restrict__ sidx,
              float* __restrict__ Yf, uint32_t* __restrict__ Yh)
{
    constexpr int KT = 64;
    constexpr int KW = KT / 2;
    constexpr int ST = 36;
    constexpr int NT = K / KT;
    constexpr int K2 = K / 2;
    constexpr int BUFW = 128 * ST;
    constexpr uint32_t STAGE_B = 2 * BUFW * 4;   // 36864 bytes per stage

    extern __shared__ uint32_t dsm[];            // 2 stages (reused by epilogue)

    const int tid  = threadIdx.x;
    const int lane = tid & 31;
    const int warp = tid >> 5;
    const int g = lane >> 2;
    const int t = lane & 3;
    const int wm = (warp & 1) * 64;
    const int wn = (warp >> 1) * 64;

    const int agent = blockIdx.z;
    const int m0 = blockIdx.y * 128;
    const int n0 = blockIdx.x * 128;
    const int s = sidx[agent] & 3;

    const uint32_t* Aha = Ah + (size_t)agent * NE * K2;
    const uint32_t* Bhs = Bh + (size_t)s * NOUT * K2;
    const float*    bs  = bias + (size_t)s * NOUT;

    const uint32_t base = smem_u32(dsm);

    float acc[4][8][4];
    #pragma unroll
    for (int mi = 0; mi < 4; ++mi)
        #pragma unroll
        for (int ni = 0; ni < 8; ++ni)
            #pragma unroll
            for (int j = 0; j < 4; ++j) acc[mi][ni][j] = 0.f;

    auto issue = [&](int ti, int buf) {
        const int kw0 = ti * KW;
        const uint32_t aB = base + (uint32_t)buf * STAGE_B;
        const uint32_t bB = aB + BUFW * 4;
        #pragma unroll
        for (int p = 0; p < 8; ++p) {
            const int idx = p * 128 + tid;
            const int row = idx >> 3;
            const int kg  = (idx & 7) * 4;
            const uint32_t so = (uint32_t)(row * ST + kg) * 4;
            cp_async16(aB + so, Aha + (size_t)(m0 + row) * K2 + kw0 + kg);
            cp_async16(bB + so, Bhs + (size_t)(n0 + row) * K2 + kw0 + kg);
        }
        cp_commit();
    };

    issue(0, 0);

    const uint32_t a_row = (uint32_t)(wm + (lane & 15));
    const uint32_t a_kw  = (uint32_t)((lane >> 4) << 2);
    const uint32_t b_row = (uint32_t)(wn + ((lane >> 4) << 3) + (lane & 7));
    const uint32_t b_kw  = (uint32_t)(((lane >> 3) & 1) << 2);

    #pragma unroll 1
    for (int ti = 0; ti < NT; ++ti) {
        if (ti + 1 < NT) { issue(ti + 1, (ti + 1) & 1); cp_wait<1>(); }
        else             { cp_wait<0>(); }
        __syncthreads();

        const uint32_t aB = base + (uint32_t)(ti & 1) * STAGE_B;
        const uint32_t bB = aB + BUFW * 4;

        #pragma unroll
        for (int ks = 0; ks < 4; ++ks) {
            const uint32_t kso = (uint32_t)(ks * 8);
            uint32_t fA[4][4];
            #pragma unroll
            for (int mi = 0; mi < 4; ++mi) {
                const uint32_t off = ((a_row + mi * 16) * ST + kso + a_kw) * 4;
                ldsm_x4(fA[mi][0], fA[mi][1], fA[mi][2], fA[mi][3], aB + off);
            }
            uint32_t fB[8][2];
            #pragma unroll
            for (int np = 0; np < 4; ++np) {
                const uint32_t off = ((b_row + np * 16) * ST + kso + b_kw) * 4;
                ldsm_x4(fB[2*np][0], fB[2*np][1], fB[2*np+1][0], fB[2*np+1][1], bB + off);
            }
            #pragma unroll
            for (int ni = 0; ni < 8; ++ni)
                #pragma unroll
                for (int mi = 0; mi < 4; ++mi)
                    mma_f16(acc[mi][ni], fA[mi], fB[ni]);
        }
        __syncthreads();
    }

    // ---- epilogue: stage in smem (conflict-free), coalesced 128b stores ----
    if (PACK_OUT) {
        // staging: [128 rows][68 words] packed fp16x2 (64 data words/row).
        uint32_t* stg = dsm;
        #pragma unroll
        for (int mi = 0; mi < 4; ++mi) {
            #pragma unroll
            for (int ni = 0; ni < 8; ++ni) {
                const int ccol = wn + ni * 8 + 2 * t;
                const float2 bb = *reinterpret_cast<const float2*>(bs + n0 + ccol);
                float v0 = acc[mi][ni][0] + bb.x;
                float v1 = acc[mi][ni][1] + bb.y;
                float v2 = acc[mi][ni][2] + bb.x;
                float v3 = acc[mi][ni][3] + bb.y;
                if (RELU) {
                    v0 = fmaxf(v0, 0.f); v1 = fmaxf(v1, 0.f);
                    v2 = fmaxf(v2, 0.f); v3 = fmaxf(v3, 0.f);
                }
                const int r = wm + mi * 16 + g;
                const int c = ccol >> 1;                 // word col 0..63
                stg[(r    ) * 68 + c] = pack2h(v0, v1);  // banks (4g+t)%32: conflict-free
                stg[(r + 8) * 68 + c] = pack2h(v2, v3);
            }
        }
        __syncthreads();
        uint32_t* Yha = Yh + (size_t)agent * NE * (NOUT / 2);
        // 128 rows x 16 uint4 = 2048 uint4; 128 threads -> 16 each, coalesced.
        #pragma unroll
        for (int p = 0; p < 16; ++p) {
            const int idx = p * 128 + tid;
            const int row = idx >> 4;
            const int c4  = idx & 15;
            const uint4 v = *reinterpret_cast<const uint4*>(&stg[row * 68 + c4 * 4]);
            *reinterpret_cast<uint4*>(
                Yha + (size_t)(m0 + row) * (NOUT / 2) + (n0 >> 1) + c4 * 4) = v;
        }
    } else {
        // staging: [128 rows][68 float2] (64 data float2/row = 128 floats).
        float2* stg = reinterpret_cast<float2*>(dsm);
        #pragma unroll
        for (int mi = 0; mi < 4; ++mi) {
            #pragma unroll
            for (int ni = 0; ni < 8; ++ni) {
                const int ccol = wn + ni * 8 + 2 * t;
                const float2 bb = *reinterpret_cast<const float2*>(bs + n0 + ccol);
                float v0 = acc[mi][ni][0] + bb.x;
                float v1 = acc[mi][ni][1] + bb.y;
                float v2 = acc[mi][ni][2] + bb.x;
                float v3 = acc[mi][ni][3] + bb.y;
                if (RELU) {
                    v0 = fmaxf(v0, 0.f); v1 = fmaxf(v1, 0.f);
                    v2 = fmaxf(v2, 0.f); v3 = fmaxf(v3, 0.f);
                }
                const int r = wm + mi * 16 + g;
                const int c = ccol >> 1;
                stg[(r    ) * 68 + c] = make_float2(v0, v1);
                stg[(r + 8) * 68 + c] = make_float2(v2, v3);
            }
        }
        __syncthreads();
        float* Yfa = Yf + (size_t)agent * NE * NOUT;
        const float* stf = reinterpret_cast<const float*>(stg);
        // 128 rows x 32 float4 = 4096 float4; 128 threads -> 32 each, coalesced.
        #pragma unroll
        for (int p = 0; p < 32; ++p) {
            const int idx = p * 128 + tid;
            const int row = idx >> 5;
            const int c4  = idx & 31;
            const float4 v = *reinterpret_cast<const float4*>(&stf[row * 136 + c4 * 4]);
            *reinterpret_cast<float4*>(
                Yfa + (size_t)(m0 + row) * NOUT + n0 + c4 * 4) = v;
        }
    }
}

} // namespace seps

extern "C" void kernel_launch(void* const* d_in, const int* in_sizes, int n_in,
                              void* d_out, int out_size)
{
    using namespace seps;
    const float* x   = (const float*)d_in[0];
    const float* W1  = (const float*)d_in[1];
    const float* b1  = (const float*)d_in[2];
    const float* W2  = (const float*)d_in[3];
    const float* b2  = (const float*)d_in[4];
    const float* W3  = (const float*)d_in[5];
    const float* b3  = (const float*)d_in[6];
    const int* sidx  = (const int*)d_in[7];
    float* out = (float*)d_out;

    uint32_t *xh, *w1h, *w2h, *w3h, *h1h, *h2h;
    cudaGetSymbolAddress((void**)&xh,  g_xh);
    cudaGetSymbolAddress((void**)&w1h, g_w1h);
    cudaGetSymbolAddress((void**)&w2h, g_w2h);
    cudaGetSymbolAddress((void**)&w3h, g_w3h);
    cudaGetSymbolAddress((void**)&h1h, g_h1h);
    cudaGetSymbolAddress((void**)&h2h, g_h2h);

    // prepass
    {
        int n4 = NA * NE * 64;
        pack_act4<<<(n4 + 255) / 256, 256>>>((const float4*)x, (uint2*)xh, n4);
        pack_wgt_fused<<<dim3(16, 32, 12), 256>>>(W1, w1h, W2, w2h, W3, w3h);
    }

    // 2 stages x 36864B = 73728B dynamic smem (also holds epilogue staging:
    // packed 128*68*4=34816B; float2 128*68*8=69632B -- both fit).
    const int dyn = 2 * 2 * 128 * 36 * 4;
    cudaFuncSetAttribute(gemm_f16< 256, 1024, true,  true >,
                         cudaFuncAttributeMaxDynamicSharedMemorySize, dyn);
    cudaFuncSetAttribute(gemm_f16<1024, 1024, true,  true >,
                         cudaFuncAttributeMaxDynamicSharedMemorySize, dyn);
    cudaFuncSetAttribute(gemm_f16<1024,  512, false, false>,
                         cudaFuncAttributeMaxDynamicSharedMemorySize, dyn);

    const dim3 blk(128);
    gemm_f16< 256, 1024, true,  true ><<<dim3(8, 32, 8), blk, dyn>>>(xh,  w1h, b1, sidx, nullptr, h1h);
    gemm_f16<1024, 1024, true,  true ><<<dim3(8, 32, 8), blk, dyn>>>(h1h, w2h, b2, sidx, nullptr, h2h);
    gemm_f16<1024,  512, false, false><<<dim3(4, 32, 8), blk, dyn>>>(h2h, w3h, b3, sidx, out, nullptr);
}

// round 16
// speedup vs baseline: 1.0341x; 1.0341x over previous
#include <cuda_runtime.h>
#include <cuda_fp16.h>
#include <cstdint>
#include <cstddef>

// MultiAgentSEPSNetwork: 8 agents x (4096,256)->1024->1024->512 MLP,
// per-agent net via seps_idx (int32 &3).
//
// Round 16 (final config): GEMM is the R14 optimum verbatim -- CTA 128x128,
// 4 warps (2Mx2N, 64x64 each), KT=64, 2-stage cp.async, 2 CTAs/SM, scattered
// async epilogue (R15's staged epilogue regressed: added sync > coalescing
// gain). Prepass fused into ONE launch: blockIdx.z==12 plane grid-strides
// the activation pack alongside the weight transpose planes.
// Math: single-term fp16, fp32 accum (rel_err 5.1e-4; gate 1e-3).

namespace seps {

constexpr int NA = 8;
constexpr int NE = 4096;

// ---- persistent device scratch ----
__device__ uint32_t g_xh [(size_t)NA * NE * 128];    // x fp16 [M][K2] words
__device__ uint32_t g_w1h[(size_t)4 * 1024 * 128];   // W^T fp16 [S][N][K2]
__device__ uint32_t g_w2h[(size_t)4 * 1024 * 512];
__device__ uint32_t g_w3h[(size_t)4 * 512 * 512];
__device__ uint32_t g_h1h[(size_t)NA * NE * 512];    // h fp16 [M][K2]
__device__ uint32_t g_h2h[(size_t)NA * NE * 512];

__device__ __forceinline__ uint32_t smem_u32(const void* p) {
    uint32_t a;
    asm("{ .reg .u64 t; cvta.to.shared.u64 t, %1; cvt.u32.u64 %0, t; }" : "=r"(a) : "l"(p));
    return a;
}
__device__ __forceinline__ uint32_t pack2h(float v0, float v1) {
    __half h0 = __float2half_rn(v0), h1 = __float2half_rn(v1);
    return (uint32_t)__half_as_ushort(h0) | ((uint32_t)__half_as_ushort(h1) << 16);
}
__device__ __forceinline__ void cp_async16(uint32_t dst, const void* src) {
    asm volatile("cp.async.cg.shared.global [%0], [%1], 16;" :: "r"(dst), "l"(src));
}
__device__ __forceinline__ void cp_commit() { asm volatile("cp.async.commit_group;"); }
template<int N> __device__ __forceinline__ void cp_wait() {
    asm volatile("cp.async.wait_group %0;" :: "n"(N));
}
__device__ __forceinline__ void mma_f16(float* c, const uint32_t* a, const uint32_t* b) {
    asm volatile(
        "mma.sync.aligned.m16n8k16.row.col.f32.f16.f16.f32 "
        "{%0,%1,%2,%3}, {%4,%5,%6,%7}, {%8,%9}, {%0,%1,%2,%3};"
        : "+f"(c[0]), "+f"(c[1]), "+f"(c[2]), "+f"(c[3])
        : "r"(a[0]), "r"(a[1]), "r"(a[2]), "r"(a[3]),
          "r"(b[0]), "r"(b[1]));
}
__device__ __forceinline__ void ldsm_x4(uint32_t& r0, uint32_t& r1, uint32_t& r2,
                                        uint32_t& r3, uint32_t addr) {
    asm volatile("ldmatrix.sync.aligned.m8n8.x4.shared.b16 {%0,%1,%2,%3}, [%4];"
                 : "=r"(r0), "=r"(r1), "=r"(r2), "=r"(r3) : "r"(addr));
}

// ---- single fused prepass ----
// z in [0,12): weight transpose+pack plane (layer = z>>2, s = z&3).
// z == 12    : activation pack, grid-strided over 16*32=512 blocks.
__global__ __launch_bounds__(256)
void prepass_fused(const float4* __restrict__ x4, uint2* __restrict__ xh2, int n4,
                   const float* __restrict__ W1, uint32_t* __restrict__ o1,
                   const float* __restrict__ W2, uint32_t* __restrict__ o2,
                   const float* __restrict__ W3, uint32_t* __restrict__ o3) {
    if (blockIdx.z == 12) {
        const int nblk = gridDim.x * gridDim.y;           // 512
        const int bid  = blockIdx.y * gridDim.x + blockIdx.x;
        for (int i = bid * blockDim.x + threadIdx.x; i < n4; i += nblk * blockDim.x) {
            float4 v = x4[i];
            xh2[i] = make_uint2(pack2h(v.x, v.y), pack2h(v.z, v.w));
        }
        return;
    }
    __shared__ uint32_t tile[32][33];
    const int layer = blockIdx.z >> 2;
    const int s     = blockIdx.z & 3;
    int K2, N;
    const float* src;
    uint32_t* dst;
    if (layer == 0)      { K2 = 128; N = 1024; src = W1; dst = o1; }
    else if (layer == 1) { K2 = 512; N = 1024; src = W2; dst = o2; }
    else                 { K2 = 512; N =  512; src = W3; dst = o3; }

    const int kw0 = blockIdx.x * 32;
    const int n0  = blockIdx.y * 32;
    if (kw0 >= K2 || n0 >= N) return;

    const int tx = threadIdx.x & 31;
    const int ty = threadIdx.x >> 5;
    const float* ws = src + (size_t)s * (2 * K2) * N;
    #pragma unroll
    for (int r = 0; r < 32; r += 8) {
        const int kw = kw0 + r + ty;
        const float v0 = ws[(size_t)(2 * kw    ) * N + n0 + tx];
        const float v1 = ws[(size_t)(2 * kw + 1) * N + n0 + tx];
        tile[tx][r + ty] = pack2h(v0, v1);                // transposed [n][kw]
    }
    __syncthreads();
    uint32_t* wd = dst + (size_t)s * N * K2;
    #pragma unroll
    for (int r = 0; r < 32; r += 8) {
        const int n = n0 + r + ty;
        wd[(size_t)n * K2 + kw0 + tx] = tile[r + ty][tx];
    }
}

// ---- GEMM: CTA 128x128, 4 warps (2Mx2N, 64x64 each), KT=64, 2-stage ----
// (R14/R12 optimum, verbatim.)
template<int K, int NOUT, bool RELU, bool PACK_OUT>
__global__ __launch_bounds__(128, 2)
void gemm_f16(const uint32_t* __restrict__ Ah, const uint32_t* __restrict__ Bh,
              const float* __restrict__ bias, const int* __restrict__ sidx,
              float* __restrict__ Yf, uint32_t* __restrict__ Yh)
{
    constexpr int KT = 64;
    constexpr int KW = KT / 2;                   // 32 words per row-stage
    constexpr int ST = 36;                       // smem row stride (words)
    constexpr int NT = K / KT;
    constexpr int K2 = K / 2;
    constexpr int BUFW = 128 * ST;               // words per operand buffer
    constexpr uint32_t STAGE_B = 2 * BUFW * 4;   // 36864 bytes per stage (A|B)

    extern __shared__ uint32_t dsm[];            // 2 stages x (A | B)

    const int tid  = threadIdx.x;
    const int lane = tid & 31;
    const int warp = tid >> 5;                   // 0..3
    const int g = lane >> 2;
    const int t = lane & 3;
    const int wm = (warp & 1) * 64;
    const int wn = (warp >> 1) * 64;

    const int agent = blockIdx.z;
    const int m0 = blockIdx.y * 128;
    const int n0 = blockIdx.x * 128;
    const int s = sidx[agent] & 3;

    const uint32_t* Aha = Ah + (size_t)agent * NE * K2;
    const uint32_t* Bhs = Bh + (size_t)s * NOUT * K2;
    const float*    bs  = bias + (size_t)s * NOUT;

    const uint32_t base = smem_u32(dsm);

    float acc[4][8][4];
    #pragma unroll
    for (int mi = 0; mi < 4; ++mi)
        #pragma unroll
        for (int ni = 0; ni < 8; ++ni)
            #pragma unroll
            for (int j = 0; j < 4; ++j) acc[mi][ni][j] = 0.f;

    auto issue = [&](int ti, int buf) {
        const int kw0 = ti * KW;
        const uint32_t aB = base + (uint32_t)buf * STAGE_B;
        const uint32_t bB = aB + BUFW * 4;
        // per operand: 128 rows x 8 chunks(16B) = 1024; 128 threads -> 8 each
        #pragma unroll
        for (int p = 0; p < 8; ++p) {
            const int idx = p * 128 + tid;
            const int row = idx >> 3;
            const int kg  = (idx & 7) * 4;
            const uint32_t so = (uint32_t)(row * ST + kg) * 4;
            cp_async16(aB + so, Aha + (size_t)(m0 + row) * K2 + kw0 + kg);
            cp_async16(bB + so, Bhs + (size_t)(n0 + row) * K2 + kw0 + kg);
        }
        cp_commit();
    };

    issue(0, 0);

    const uint32_t a_row = (uint32_t)(wm + (lane & 15));
    const uint32_t a_kw  = (uint32_t)((lane >> 4) << 2);
    const uint32_t b_row = (uint32_t)(wn + ((lane >> 4) << 3) + (lane & 7));
    const uint32_t b_kw  = (uint32_t)(((lane >> 3) & 1) << 2);

    #pragma unroll 1
    for (int ti = 0; ti < NT; ++ti) {
        if (ti + 1 < NT) { issue(ti + 1, (ti + 1) & 1); cp_wait<1>(); }
        else             { cp_wait<0>(); }
        __syncthreads();

        const uint32_t aB = base + (uint32_t)(ti & 1) * STAGE_B;
        const uint32_t bB = aB + BUFW * 4;

        #pragma unroll
        for (int ks = 0; ks < 4; ++ks) {          // 4 x k16 per stage
            const uint32_t kso = (uint32_t)(ks * 8);
            uint32_t fA[4][4];
            #pragma unroll
            for (int mi = 0; mi < 4; ++mi) {
                const uint32_t off = ((a_row + mi * 16) * ST + kso + a_kw) * 4;
                ldsm_x4(fA[mi][0], fA[mi][1], fA[mi][2], fA[mi][3], aB + off);
            }
            uint32_t fB[8][2];
            #pragma unroll
            for (int np = 0; np < 4; ++np) {
                const uint32_t off = ((b_row + np * 16) * ST + kso + b_kw) * 4;
                ldsm_x4(fB[2*np][0], fB[2*np][1], fB[2*np+1][0], fB[2*np+1][1], bB + off);
            }
            #pragma unroll
            for (int ni = 0; ni < 8; ++ni)
                #pragma unroll
                for (int mi = 0; mi < 4; ++mi)
                    mma_f16(acc[mi][ni], fA[mi], fB[ni]);
        }
        __syncthreads();
    }

    // ---- epilogue (R14: scattered async stores; staged version regressed) ----
    float*    Yfa = PACK_OUT ? nullptr : (Yf + (size_t)agent * NE * NOUT);
    uint32_t* Yha = PACK_OUT ? (Yh + (size_t)agent * NE * (NOUT / 2)) : nullptr;

    #pragma unroll
    for (int mi = 0; mi < 4; ++mi) {
        const int r = m0 + wm + mi * 16 + g;
        #pragma unroll
        for (int ni = 0; ni < 8; ++ni) {
            const int ccol = n0 + wn + ni * 8 + 2 * t;
            const float2 bb = *reinterpret_cast<const float2*>(bs + ccol);
            float v0 = acc[mi][ni][0] + bb.x;
            float v1 = acc[mi][ni][1] + bb.y;
            float v2 = acc[mi][ni][2] + bb.x;
            float v3 = acc[mi][ni][3] + bb.y;
            if (RELU) {
                v0 = fmaxf(v0, 0.f); v1 = fmaxf(v1, 0.f);
                v2 = fmaxf(v2, 0.f); v3 = fmaxf(v3, 0.f);
            }
            if (PACK_OUT) {
                Yha[(size_t)(r    ) * (NOUT / 2) + ccol / 2] = pack2h(v0, v1);
                Yha[(size_t)(r + 8) * (NOUT / 2) + ccol / 2] = pack2h(v2, v3);
            } else {
                *reinterpret_cast<float2*>(Yfa + (size_t)(r    ) * NOUT + ccol) = make_float2(v0, v1);
                *reinterpret_cast<float2*>(Yfa + (size_t)(r + 8) * NOUT + ccol) = make_float2(v2, v3);
            }
        }
    }
}

} // namespace seps

extern "C" void kernel_launch(void* const* d_in, const int* in_sizes, int n_in,
                              void* d_out, int out_size)
{
    using namespace seps;
    const float* x   = (const float*)d_in[0];
    const float* W1  = (const float*)d_in[1];
    const float* b1  = (const float*)d_in[2];
    const float* W2  = (const float*)d_in[3];
    const float* b2  = (const float*)d_in[4];
    const float* W3  = (const float*)d_in[5];
    const float* b3  = (const float*)d_in[6];
    const int* sidx  = (const int*)d_in[7];
    float* out = (float*)d_out;

    uint32_t *xh, *w1h, *w2h, *w3h, *h1h, *h2h;
    cudaGetSymbolAddress((void**)&xh,  g_xh);
    cudaGetSymbolAddress((void**)&w1h, g_w1h);
    cudaGetSymbolAddress((void**)&w2h, g_w2h);
    cudaGetSymbolAddress((void**)&w3h, g_w3h);
    cudaGetSymbolAddress((void**)&h1h, g_h1h);
    cudaGetSymbolAddress((void**)&h2h, g_h2h);

    // single fused prepass launch: z<12 weight planes, z==12 activation pack
    {
        const int n4 = NA * NE * 64;   // float4 count in x
        prepass_fused<<<dim3(16, 32, 13), 256>>>(
            (const float4*)x, (uint2*)xh, n4, W1, w1h, W2, w2h, W3, w3h);
    }

    // 2 stages x (A 18432B + B 18432B) = 73728 bytes dynamic smem
    const int dyn = 2 * 2 * 128 * 36 * 4;
    cudaFuncSetAttribute(gemm_f16< 256, 1024, true,  true >,
                         cudaFuncAttributeMaxDynamicSharedMemorySize, dyn);
    cudaFuncSetAttribute(gemm_f16<1024, 1024, true,  true >,
                         cudaFuncAttributeMaxDynamicSharedMemorySize, dyn);
    cudaFuncSetAttribute(gemm_f16<1024,  512, false, false>,
                         cudaFuncAttributeMaxDynamicSharedMemorySize, dyn);

    const dim3 blk(128);
    // grids: (NOUT/128, NE/128, agents)
    gemm_f16< 256, 1024, true,  true ><<<dim3(8, 32, 8), blk, dyn>>>(xh,  w1h, b1, sidx, nullptr, h1h);
    gemm_f16<1024, 1024, true,  true ><<<dim3(8, 32, 8), blk, dyn>>>(h1h, w2h, b2, sidx, nullptr, h2h);
    gemm_f16<1024,  512, false, false><<<dim3(4, 32, 8), blk, dyn>>>(h2h, w3h, b3, sidx, out, nullptr);
}